// round 15
// baseline (speedup 1.0000x reference)
#include <cuda_runtime.h>
#include <cuda_bf16.h>
#include <cstdint>

#define N_NODES 50000
#define IN_F    256
#define OUT_F   64
#define MAX_E   800000
#define SCAN_B  ((N_NODES + 255) / 256)   // 196
#define TILE_M  128
// row split between the HMMA kernel and the scalar-FFMA kernel (pipe overlap)
#define MMA_ROWS 35200                    // 275 * 128
#define MMA_BLOCKS (MMA_ROWS / TILE_M)    // 275
#define SCAL_ROWS (N_NODES - MMA_ROWS)    // 14800
#define SCAL_RPB 32
#define SCAL_BLOCKS ((SCAL_ROWS + SCAL_RPB - 1) / SCAL_RPB)  // 463

// smem pitch: 72 bf16 = 144B = 36 banks -> fragment loads conflict-free
#define APITCH 72
#define SM_A_HI 0
#define SM_A_LO (128 * APITCH)
#define SM_B    (2 * 128 * APITCH)
#define SM_ELEMS (SM_B + 4 * 64 * APITCH)
#define SM_BYTES (SM_ELEMS * 2)          // 73728 B

// ---- __device__ scratch (alloc-guard-safe) ----
// interleaved messages: [node][0..63]=miu*att, [node][64..127]=sigma*att^2
__device__ __align__(16) float g_msg[N_NODES * 128];
__device__ int  g_cnt[N_NODES];
__device__ int  g_off[N_NODES + 1];
__device__ int  g_cur[N_NODES];
__device__ int  g_bsum[SCAN_B];
__device__ __align__(16) int4 g_edges[MAX_E];
__device__ int  g_is64;
// weight fragments, k-contiguous [n][k]: [0]=Wm_hi [1]=Wm_lo [2]=Ws_hi [3]=Ws_lo
__device__ __align__(16) __nv_bfloat16 g_wfrag[4][OUT_F * IN_F];

__device__ __forceinline__ int load_idx(const void* p, int i, int is64)
{ return is64 ? (int)((const long long*)p)[i] : ((const int*)p)[i]; }

// ======= probe (block 0, thread 0) fused with counter zeroing =======
__global__ __launch_bounds__(256) void probe_zero_kernel(const void* __restrict__ esrc)
{
    const int i = blockIdx.x * 256 + threadIdx.x;
    if (i == 0) {
        const long long* p = (const long long*)esrc;
        int ok64 = 1;
        for (int j = 0; j < 32; j++) {
            long long v = p[j];
            if (v < 0 || v >= N_NODES) { ok64 = 0; break; }
        }
        g_is64 = ok64;
    }
    if (i < N_NODES) g_cnt[i] = 0;
}
__global__ __launch_bounds__(256) void hist_kernel(const void* __restrict__ edst, int E)
{
    const int i = blockIdx.x * 256 + threadIdx.x;
    if (i >= E) return;
    const int d = load_idx(edst, i, g_is64);
    if ((unsigned)d < N_NODES) atomicAdd(&g_cnt[d], 1);
}
__global__ __launch_bounds__(256) void scan1_kernel()
{
    __shared__ int wsum[8];
    const int tid = threadIdx.x, lane = tid & 31, wid = tid >> 5;
    const int i = blockIdx.x * 256 + tid;
    const int val = (i < N_NODES) ? g_cnt[i] : 0;
    int v = val;
#pragma unroll
    for (int o = 1; o < 32; o <<= 1) { int n = __shfl_up_sync(~0u, v, o); if (lane >= o) v += n; }
    if (lane == 31) wsum[wid] = v;
    __syncthreads();
    if (wid == 0) {
        int w = (lane < 8) ? wsum[lane] : 0;
#pragma unroll
        for (int o = 1; o < 8; o <<= 1) { int n = __shfl_up_sync(~0u, w, o); if (lane >= o) w += n; }
        if (lane < 8) wsum[lane] = w;
    }
    __syncthreads();
    const int wb = (wid > 0) ? wsum[wid - 1] : 0;
    if (i < N_NODES) g_off[i] = wb + v - val;
    if (tid == 255) g_bsum[blockIdx.x] = wsum[7];
}
__global__ __launch_bounds__(256) void scan2_kernel()
{
    __shared__ int wsum[8];
    const int tid = threadIdx.x, lane = tid & 31, wid = tid >> 5;
    const int val = (tid < SCAN_B) ? g_bsum[tid] : 0;
    int v = val;
#pragma unroll
    for (int o = 1; o < 32; o <<= 1) { int n = __shfl_up_sync(~0u, v, o); if (lane >= o) v += n; }
    if (lane == 31) wsum[wid] = v;
    __syncthreads();
    if (wid == 0) {
        int w = (lane < 8) ? wsum[lane] : 0;
#pragma unroll
        for (int o = 1; o < 8; o <<= 1) { int n = __shfl_up_sync(~0u, w, o); if (lane >= o) w += n; }
        if (lane < 8) wsum[lane] = w;
    }
    __syncthreads();
    const int wb = (wid > 0) ? wsum[wid - 1] : 0;
    if (tid < SCAN_B) g_bsum[tid] = wb + v - val;
    if (tid == 255) g_off[N_NODES] = wsum[7];
}
__global__ __launch_bounds__(256) void scan3_kernel()
{
    const int i = blockIdx.x * 256 + threadIdx.x;
    if (i >= N_NODES) return;
    const int o = g_off[i] + g_bsum[blockIdx.x];
    g_off[i] = o;
    g_cur[i] = o;
}
__global__ __launch_bounds__(256) void fill_kernel(
    const void* __restrict__ esrc, const void* __restrict__ edst,
    const float* __restrict__ a1, const float* __restrict__ a2, int E)
{
    const int i = blockIdx.x * 256 + threadIdx.x;
    if (i >= E) return;
    const int is64 = g_is64;
    const int s = load_idx(esrc, i, is64);
    const int d = load_idx(edst, i, is64);
    if ((unsigned)s >= N_NODES || (unsigned)d >= N_NODES) return;
    const int pos = atomicAdd(&g_cur[d], 1);
    g_edges[pos] = make_int4(s, __float_as_int(__ldg(a1 + i)),
                                __float_as_int(__ldg(a2 + i)), 0);
}

// ===== weight prep: W[k][n] f32 -> hi/lo bf16 in [n][k] k-contiguous layout =====
__global__ __launch_bounds__(256) void prep_w_kernel(
    const float* __restrict__ wm, const float* __restrict__ ws)
{
    const int i = blockIdx.x * 256 + threadIdx.x;   // 32768
    if (i >= 2 * OUT_F * IN_F) return;
    const int mat = i >> 14;
    const int r   = i & 16383;
    const int n   = r >> 8;
    const int k   = r & 255;
    const float v = (mat ? ws : wm)[k * OUT_F + n];
    const __nv_bfloat16 h = __float2bfloat16(v);
    const __nv_bfloat16 l = __float2bfloat16(v - __bfloat162float(h));
    g_wfrag[mat * 2 + 0][n * IN_F + k] = h;
    g_wfrag[mat * 2 + 1][n * IN_F + k] = l;
}

// =========== HMMA dual-GEMM (rows [0, MMA_ROWS)) — validated R11 ===========
__device__ __forceinline__ void mma16816(float* c, const uint32_t* a,
                                         uint32_t b0, uint32_t b1)
{
    asm volatile(
        "mma.sync.aligned.m16n8k16.row.col.f32.bf16.bf16.f32 "
        "{%0,%1,%2,%3}, {%4,%5,%6,%7}, {%8,%9}, {%0,%1,%2,%3};"
        : "+f"(c[0]), "+f"(c[1]), "+f"(c[2]), "+f"(c[3])
        : "r"(a[0]), "r"(a[1]), "r"(a[2]), "r"(a[3]), "r"(b0), "r"(b1));
}

__global__ __launch_bounds__(256, 2) void gemm_mma_kernel(const float* __restrict__ feat)
{
    extern __shared__ __nv_bfloat16 sm[];
    __nv_bfloat16* Ah = sm + SM_A_HI;
    __nv_bfloat16* Al = sm + SM_A_LO;
    __nv_bfloat16* Bs = sm + SM_B;

    const int tid  = threadIdx.x;
    const int wid  = tid >> 5;
    const int lane = tid & 31;
    const int gid  = lane >> 2;
    const int tq   = lane & 3;
    const int row0 = blockIdx.x * TILE_M;
    const int wr   = wid * 16;

    float accM[8][4], accS[8][4];
#pragma unroll
    for (int t = 0; t < 8; t++)
#pragma unroll
        for (int j = 0; j < 4; j++) { accM[t][j] = 0.f; accS[t][j] = 0.f; }

    for (int kc = 0; kc < 4; kc++) {
        {
            const float4* gf = (const float4*)(feat + (size_t)row0 * IN_F);
#pragma unroll
            for (int it = 0; it < 8; it++) {
                const int e  = tid + it * 256;
                const int r  = e >> 4;
                const int kg = e & 15;
                const float4 f = gf[r * 64 + kc * 16 + kg];
                const __nv_bfloat16 h0 = __float2bfloat16(f.x);
                const __nv_bfloat16 h1 = __float2bfloat16(f.y);
                const __nv_bfloat16 h2 = __float2bfloat16(f.z);
                const __nv_bfloat16 h3 = __float2bfloat16(f.w);
                __nv_bfloat162 hp[2] = { __nv_bfloat162(h0, h1), __nv_bfloat162(h2, h3) };
                __nv_bfloat162 lp[2] = {
                    __nv_bfloat162(__float2bfloat16(f.x - __bfloat162float(h0)),
                                   __float2bfloat16(f.y - __bfloat162float(h1))),
                    __nv_bfloat162(__float2bfloat16(f.z - __bfloat162float(h2)),
                                   __float2bfloat16(f.w - __bfloat162float(h3))) };
                *(uint2*)(Ah + r * APITCH + kg * 4) = *(uint2*)hp;
                *(uint2*)(Al + r * APITCH + kg * 4) = *(uint2*)lp;
            }
        }
#pragma unroll
        for (int it = 0; it < 16; it++) {
            const int e   = tid + it * 256;
            const int buf = e >> 10;
            const int r   = (e >> 4) & 63;
            const int kg  = e & 15;
            *(uint2*)(Bs + (buf * 64 + r) * APITCH + kg * 4) =
                *(const uint2*)(&g_wfrag[buf][r * IN_F + kc * 64 + kg * 4]);
        }
        __syncthreads();

#pragma unroll
        for (int ks = 0; ks < 4; ks++) {
            const int k0 = ks * 16 + tq * 2;
            uint32_t ah[4], al[4];
            const __nv_bfloat16* ar = Ah + (wr + gid) * APITCH;
            ah[0] = *(const uint32_t*)(ar + k0);
            ah[1] = *(const uint32_t*)(ar + 8 * APITCH + k0);
            ah[2] = *(const uint32_t*)(ar + k0 + 8);
            ah[3] = *(const uint32_t*)(ar + 8 * APITCH + k0 + 8);
            const __nv_bfloat16* arl = Al + (wr + gid) * APITCH;
            al[0] = *(const uint32_t*)(arl + k0);
            al[1] = *(const uint32_t*)(arl + 8 * APITCH + k0);
            al[2] = *(const uint32_t*)(arl + k0 + 8);
            al[3] = *(const uint32_t*)(arl + 8 * APITCH + k0 + 8);

#pragma unroll
            for (int nt = 0; nt < 8; nt++) {
                const int n = nt * 8 + gid;
                const __nv_bfloat16* b0p = Bs + n * APITCH;
                const __nv_bfloat16* b1p = Bs + (64 + n) * APITCH;
                const __nv_bfloat16* b2p = Bs + (128 + n) * APITCH;
                const __nv_bfloat16* b3p = Bs + (192 + n) * APITCH;
                const uint32_t mh0 = *(const uint32_t*)(b0p + k0);
                const uint32_t mh1 = *(const uint32_t*)(b0p + k0 + 8);
                const uint32_t ml0 = *(const uint32_t*)(b1p + k0);
                const uint32_t ml1 = *(const uint32_t*)(b1p + k0 + 8);
                const uint32_t sh0 = *(const uint32_t*)(b2p + k0);
                const uint32_t sh1 = *(const uint32_t*)(b2p + k0 + 8);
                const uint32_t sl0 = *(const uint32_t*)(b3p + k0);
                const uint32_t sl1 = *(const uint32_t*)(b3p + k0 + 8);
                mma16816(accM[nt], ah, mh0, mh1);
                mma16816(accM[nt], al, mh0, mh1);
                mma16816(accM[nt], ah, ml0, ml1);
                mma16816(accS[nt], ah, sh0, sh1);
                mma16816(accS[nt], al, sh0, sh1);
                mma16816(accS[nt], ah, sl0, sl1);
            }
        }
        __syncthreads();
    }

#pragma unroll
    for (int t = 0; t < 8; t++) {
        const int n = t * 8 + tq * 2;
#pragma unroll
        for (int h = 0; h < 2; h++) {
            const int row = row0 + wr + gid + h * 8;
            {
                const float s0 = fmaxf(accS[t][2 * h + 0], 0.f);
                const float s1 = fmaxf(accS[t][2 * h + 1], 0.f);
                const float a0 = expf(-s0), a1 = expf(-s1);
                const float m0 = accM[t][2 * h + 0];
                const float m1 = accM[t][2 * h + 1];
                const float mi0 = (m0 > 0.f) ? m0 : (expf(m0) - 1.f);
                const float mi1 = (m1 > 0.f) ? m1 : (expf(m1) - 1.f);
                float* rowp = g_msg + (size_t)row * 128;
                *(float2*)(rowp + n)      = make_float2(mi0 * a0, mi1 * a1);
                *(float2*)(rowp + 64 + n) = make_float2(s0 * a0 * a0, s1 * a1 * a1);
            }
        }
    }
}

// ==== scalar FFMA dual-GEMM (rows [MMA_ROWS, N)) — validated R8, FMA pipe ====
__global__ __launch_bounds__(256) void gemm_scalar_kernel(
    const float* __restrict__ feat,
    const float* __restrict__ wm,
    const float* __restrict__ ws)
{
    __shared__ float fs[SCAL_RPB * IN_F];
    const int row0 = MMA_ROWS + blockIdx.x * SCAL_RPB;
    const int tid  = threadIdx.x;
    const int nrows = min(SCAL_RPB, N_NODES - row0);

    {
        const float4* gf  = (const float4*)(feat + (size_t)row0 * IN_F);
        float4*       fs4 = (float4*)fs;
        const int total4  = nrows * (IN_F / 4);
        for (int i = tid; i < total4; i += 256) fs4[i] = gf[i];
    }
    __syncthreads();

    const int f  = tid & 63;
    const int rg = tid >> 6;

    float accm[8], accs[8];
#pragma unroll
    for (int r = 0; r < 8; r++) { accm[r] = 0.f; accs[r] = 0.f; }

    const float4* fs4 = (const float4*)fs;

    for (int k = 0; k < IN_F; k += 4) {
        const float wm0 = __ldg(&wm[(k + 0) * OUT_F + f]);
        const float wm1 = __ldg(&wm[(k + 1) * OUT_F + f]);
        const float wm2 = __ldg(&wm[(k + 2) * OUT_F + f]);
        const float wm3 = __ldg(&wm[(k + 3) * OUT_F + f]);
        const float ws0 = __ldg(&ws[(k + 0) * OUT_F + f]);
        const float ws1 = __ldg(&ws[(k + 1) * OUT_F + f]);
        const float ws2 = __ldg(&ws[(k + 2) * OUT_F + f]);
        const float ws3 = __ldg(&ws[(k + 3) * OUT_F + f]);
#pragma unroll
        for (int r = 0; r < 8; r++) {
            const float4 fv = fs4[(rg * 8 + r) * (IN_F / 4) + (k >> 2)];
            accm[r] = fmaf(fv.x, wm0, fmaf(fv.y, wm1, fmaf(fv.z, wm2, fmaf(fv.w, wm3, accm[r]))));
            accs[r] = fmaf(fv.x, ws0, fmaf(fv.y, ws1, fmaf(fv.z, ws2, fmaf(fv.w, ws3, accs[r]))));
        }
    }

#pragma unroll
    for (int r = 0; r < 8; r++) {
        const int row = row0 + rg * 8 + r;
        if (row < N_NODES) {
            const float m   = accm[r];
            const float mi  = (m > 0.f) ? m : (expf(m) - 1.f);
            const float s   = (accs[r] > 0.f) ? accs[r] : 0.f;
            const float att = expf(-s);
            float* rowp = g_msg + (size_t)row * 128;
            rowp[f]      = mi * att;
            rowp[64 + f] = s * att * att;
        }
    }
}

// =================== CSR gather (validated R11) ===================
__global__ __launch_bounds__(256) void gather_kernel(float* __restrict__ out)
{
    const int w = (blockIdx.x * 256 + threadIdx.x) >> 5;
    if (w >= N_NODES) return;
    const int lane = threadIdx.x & 31;
    const bool isMiu = lane < 16;

    const int beg = g_off[w];
    const int end = g_off[w + 1];

    float4 acc = make_float4(0.f, 0.f, 0.f, 0.f);
    for (int j = beg; j < end; j++) {
        const int4 ed = g_edges[j];
        const float sc = isMiu ? __int_as_float(ed.y) : __int_as_float(ed.z);
        const float4 v = ((const float4*)(g_msg + (size_t)ed.x * 128))[lane];
        acc.x = fmaf(v.x, sc, acc.x);
        acc.y = fmaf(v.y, sc, acc.y);
        acc.z = fmaf(v.z, sc, acc.z);
        acc.w = fmaf(v.w, sc, acc.w);
    }

    float* dstb = isMiu ? out + (size_t)w * OUT_F + lane * 4
                        : out + ((size_t)N_NODES + w) * OUT_F + (lane - 16) * 4;
    *(float4*)dstb = acc;
}

// ====== launch: build on s1, scalar GEMM on s2, HMMA GEMM on main ======
extern "C" void kernel_launch(void* const* d_in, const int* in_sizes, int n_in,
                              void* d_out, int out_size)
{
    const float* feat = (const float*)d_in[0];
    const void*  esrc = d_in[1];
    const void*  edst = d_in[2];
    const float* a1   = (const float*)d_in[3];
    const float* a2   = (const float*)d_in[4];
    const float* wm   = (const float*)d_in[5];
    const float* ws   = (const float*)d_in[6];
    float*       out  = (float*)d_out;
    const int E = in_sizes[3];

    static int inited = 0;
    static cudaStream_t s1, s2;
    static cudaEvent_t eFork, eJoin1, eJoin2;
    if (!inited) {
        cudaFuncSetAttribute(gemm_mma_kernel,
                             cudaFuncAttributeMaxDynamicSharedMemorySize, SM_BYTES);
        cudaStreamCreateWithFlags(&s1, cudaStreamNonBlocking);
        cudaStreamCreateWithFlags(&s2, cudaStreamNonBlocking);
        cudaEventCreateWithFlags(&eFork, cudaEventDisableTiming);
        cudaEventCreateWithFlags(&eJoin1, cudaEventDisableTiming);
        cudaEventCreateWithFlags(&eJoin2, cudaEventDisableTiming);
        inited = 1;
    }

    cudaEventRecord(eFork, 0);
    cudaStreamWaitEvent(s1, eFork, 0);
    cudaStreamWaitEvent(s2, eFork, 0);

    // s1: CSR build
    probe_zero_kernel<<<SCAN_B, 256, 0, s1>>>(esrc);
    hist_kernel<<<(E + 255) / 256, 256, 0, s1>>>(edst, E);
    scan1_kernel<<<SCAN_B, 256, 0, s1>>>();
    scan2_kernel<<<1, 256, 0, s1>>>();
    scan3_kernel<<<SCAN_B, 256, 0, s1>>>();
    fill_kernel<<<(E + 255) / 256, 256, 0, s1>>>(esrc, edst, a1, a2, E);
    cudaEventRecord(eJoin1, s1);

    // s2: scalar-FFMA GEMM for the tail rows (reads raw f32 weights)
    gemm_scalar_kernel<<<SCAL_BLOCKS, 256, 0, s2>>>(feat, wm, ws);
    cudaEventRecord(eJoin2, s2);

    // main: HMMA GEMM for the head rows
    prep_w_kernel<<<128, 256>>>(wm, ws);
    gemm_mma_kernel<<<MMA_BLOCKS, 256, SM_BYTES>>>(feat);

    // join: gather needs CSR + all messages
    cudaStreamWaitEvent(0, eJoin1, 0);
    cudaStreamWaitEvent(0, eJoin2, 0);
    const long long threads = (long long)N_NODES * 32;
    gather_kernel<<<(int)((threads + 255) / 256), 256>>>(out);
}

// round 16
// speedup vs baseline: 1.0631x; 1.0631x over previous
#include <cuda_runtime.h>
#include <cuda_bf16.h>
#include <cstdint>

#define N_NODES 50000
#define IN_F    256
#define OUT_F   64
#define MAX_E   800000
#define SCAN_B  ((N_NODES + 255) / 256)   // 196
#define TILE_M  128
#define GEMM_BLOCKS ((N_NODES + TILE_M - 1) / TILE_M)  // 391

// smem pitch: 72 bf16 = 144B = 36 banks -> fragment loads conflict-free
#define APITCH 72
#define SM_A_HI 0
#define SM_A_LO (128 * APITCH)
#define SM_B    (2 * 128 * APITCH)
#define SM_ELEMS (SM_B + 4 * 64 * APITCH)
#define SM_BYTES (SM_ELEMS * 2)          // 73728 B

// ---- __device__ scratch (alloc-guard-safe) ----
// interleaved messages: [node][0..63]=miu*att, [node][64..127]=sigma*att^2
__device__ __align__(16) float g_msg[N_NODES * 128];
__device__ int  g_cnt[N_NODES];
__device__ int  g_off[N_NODES + 1];
__device__ int  g_cur[N_NODES];
__device__ int  g_bsum[SCAN_B];
__device__ __align__(16) int4 g_edges[MAX_E];
__device__ int  g_is64;
// weight fragments, k-contiguous [n][k]: [0]=Wm_hi [1]=Wm_lo [2]=Ws_hi [3]=Ws_lo
__device__ __align__(16) __nv_bfloat16 g_wfrag[4][OUT_F * IN_F];

__device__ __forceinline__ int load_idx(const void* p, int i, int is64)
{ return is64 ? (int)((const long long*)p)[i] : ((const int*)p)[i]; }

// ==== kernel #1: dtype probe + counter zeroing + weight hi/lo prep (fused) ====
__global__ __launch_bounds__(256) void probe_zero_prep_kernel(
    const void* __restrict__ esrc,
    const float* __restrict__ wm, const float* __restrict__ ws)
{
    const int i = blockIdx.x * 256 + threadIdx.x;
    if (i == 0) {
        const long long* p = (const long long*)esrc;
        int ok64 = 1;
        for (int j = 0; j < 32; j++) {
            long long v = p[j];
            if (v < 0 || v >= N_NODES) { ok64 = 0; break; }
        }
        g_is64 = ok64;
    }
    if (i < N_NODES) g_cnt[i] = 0;
    // weight prep: 2*64*256 = 32768 conversions, one per thread
    if (i < 2 * OUT_F * IN_F) {
        const int mat = i >> 14;
        const int r   = i & 16383;
        const int n   = r >> 8;
        const int k   = r & 255;
        const float v = (mat ? ws : wm)[k * OUT_F + n];
        const __nv_bfloat16 h = __float2bfloat16(v);
        const __nv_bfloat16 l = __float2bfloat16(v - __bfloat162float(h));
        g_wfrag[mat * 2 + 0][n * IN_F + k] = h;
        g_wfrag[mat * 2 + 1][n * IN_F + k] = l;
    }
}
__global__ __launch_bounds__(256) void hist_kernel(const void* __restrict__ edst, int E)
{
    const int i = blockIdx.x * 256 + threadIdx.x;
    if (i >= E) return;
    const int d = load_idx(edst, i, g_is64);
    if ((unsigned)d < N_NODES) atomicAdd(&g_cnt[d], 1);
}
__global__ __launch_bounds__(256) void scan1_kernel()
{
    __shared__ int wsum[8];
    const int tid = threadIdx.x, lane = tid & 31, wid = tid >> 5;
    const int i = blockIdx.x * 256 + tid;
    const int val = (i < N_NODES) ? g_cnt[i] : 0;
    int v = val;
#pragma unroll
    for (int o = 1; o < 32; o <<= 1) { int n = __shfl_up_sync(~0u, v, o); if (lane >= o) v += n; }
    if (lane == 31) wsum[wid] = v;
    __syncthreads();
    if (wid == 0) {
        int w = (lane < 8) ? wsum[lane] : 0;
#pragma unroll
        for (int o = 1; o < 8; o <<= 1) { int n = __shfl_up_sync(~0u, w, o); if (lane >= o) w += n; }
        if (lane < 8) wsum[lane] = w;
    }
    __syncthreads();
    const int wb = (wid > 0) ? wsum[wid - 1] : 0;
    if (i < N_NODES) g_off[i] = wb + v - val;
    if (tid == 255) g_bsum[blockIdx.x] = wsum[7];
}
__global__ __launch_bounds__(256) void scan2_kernel()
{
    __shared__ int wsum[8];
    const int tid = threadIdx.x, lane = tid & 31, wid = tid >> 5;
    const int val = (tid < SCAN_B) ? g_bsum[tid] : 0;
    int v = val;
#pragma unroll
    for (int o = 1; o < 32; o <<= 1) { int n = __shfl_up_sync(~0u, v, o); if (lane >= o) v += n; }
    if (lane == 31) wsum[wid] = v;
    __syncthreads();
    if (wid == 0) {
        int w = (lane < 8) ? wsum[lane] : 0;
#pragma unroll
        for (int o = 1; o < 8; o <<= 1) { int n = __shfl_up_sync(~0u, w, o); if (lane >= o) w += n; }
        if (lane < 8) wsum[lane] = w;
    }
    __syncthreads();
    const int wb = (wid > 0) ? wsum[wid - 1] : 0;
    if (tid < SCAN_B) g_bsum[tid] = wb + v - val;
    if (tid == 255) g_off[N_NODES] = wsum[7];
}
__global__ __launch_bounds__(256) void scan3_kernel()
{
    const int i = blockIdx.x * 256 + threadIdx.x;
    if (i >= N_NODES) return;
    const int o = g_off[i] + g_bsum[blockIdx.x];
    g_off[i] = o;
    g_cur[i] = o;
}
__global__ __launch_bounds__(256) void fill_kernel(
    const void* __restrict__ esrc, const void* __restrict__ edst,
    const float* __restrict__ a1, const float* __restrict__ a2, int E)
{
    const int i = blockIdx.x * 256 + threadIdx.x;
    if (i >= E) return;
    const int is64 = g_is64;
    const int s = load_idx(esrc, i, is64);
    const int d = load_idx(edst, i, is64);
    if ((unsigned)s >= N_NODES || (unsigned)d >= N_NODES) return;
    const int pos = atomicAdd(&g_cur[d], 1);
    g_edges[pos] = make_int4(s, __float_as_int(__ldg(a1 + i)),
                                __float_as_int(__ldg(a2 + i)), 0);
}

// =========== HMMA dual-GEMM, all rows — validated R11 configuration ==========
__device__ __forceinline__ void mma16816(float* c, const uint32_t* a,
                                         uint32_t b0, uint32_t b1)
{
    asm volatile(
        "mma.sync.aligned.m16n8k16.row.col.f32.bf16.bf16.f32 "
        "{%0,%1,%2,%3}, {%4,%5,%6,%7}, {%8,%9}, {%0,%1,%2,%3};"
        : "+f"(c[0]), "+f"(c[1]), "+f"(c[2]), "+f"(c[3])
        : "r"(a[0]), "r"(a[1]), "r"(a[2]), "r"(a[3]), "r"(b0), "r"(b1));
}

__global__ __launch_bounds__(256, 2) void gemm_mma_kernel(const float* __restrict__ feat)
{
    extern __shared__ __nv_bfloat16 sm[];
    __nv_bfloat16* Ah = sm + SM_A_HI;
    __nv_bfloat16* Al = sm + SM_A_LO;
    __nv_bfloat16* Bs = sm + SM_B;

    const int tid  = threadIdx.x;
    const int wid  = tid >> 5;
    const int lane = tid & 31;
    const int gid  = lane >> 2;
    const int tq   = lane & 3;
    const int row0 = blockIdx.x * TILE_M;
    const int nrows = min(TILE_M, N_NODES - row0);
    const int wr   = wid * 16;

    float accM[8][4], accS[8][4];
#pragma unroll
    for (int t = 0; t < 8; t++)
#pragma unroll
        for (int j = 0; j < 4; j++) { accM[t][j] = 0.f; accS[t][j] = 0.f; }

    for (int kc = 0; kc < 4; kc++) {
        {
            const float4* gf = (const float4*)(feat + (size_t)row0 * IN_F);
#pragma unroll
            for (int it = 0; it < 8; it++) {
                const int e  = tid + it * 256;
                const int r  = e >> 4;
                const int kg = e & 15;
                __nv_bfloat162 hp[2], lp[2];
                if (r < nrows) {
                    const float4 f = gf[r * 64 + kc * 16 + kg];
                    const __nv_bfloat16 h0 = __float2bfloat16(f.x);
                    const __nv_bfloat16 h1 = __float2bfloat16(f.y);
                    const __nv_bfloat16 h2 = __float2bfloat16(f.z);
                    const __nv_bfloat16 h3 = __float2bfloat16(f.w);
                    hp[0] = __nv_bfloat162(h0, h1); hp[1] = __nv_bfloat162(h2, h3);
                    lp[0] = __nv_bfloat162(__float2bfloat16(f.x - __bfloat162float(h0)),
                                           __float2bfloat16(f.y - __bfloat162float(h1)));
                    lp[1] = __nv_bfloat162(__float2bfloat16(f.z - __bfloat162float(h2)),
                                           __float2bfloat16(f.w - __bfloat162float(h3)));
                } else {
                    hp[0] = hp[1] = lp[0] = lp[1] = __nv_bfloat162(__nv_bfloat16(0.f), __nv_bfloat16(0.f));
                }
                *(uint2*)(Ah + r * APITCH + kg * 4) = *(uint2*)hp;
                *(uint2*)(Al + r * APITCH + kg * 4) = *(uint2*)lp;
            }
        }
#pragma unroll
        for (int it = 0; it < 16; it++) {
            const int e   = tid + it * 256;
            const int buf = e >> 10;
            const int r   = (e >> 4) & 63;
            const int kg  = e & 15;
            *(uint2*)(Bs + (buf * 64 + r) * APITCH + kg * 4) =
                *(const uint2*)(&g_wfrag[buf][r * IN_F + kc * 64 + kg * 4]);
        }
        __syncthreads();

#pragma unroll
        for (int ks = 0; ks < 4; ks++) {
            const int k0 = ks * 16 + tq * 2;
            uint32_t ah[4], al[4];
            const __nv_bfloat16* ar = Ah + (wr + gid) * APITCH;
            ah[0] = *(const uint32_t*)(ar + k0);
            ah[1] = *(const uint32_t*)(ar + 8 * APITCH + k0);
            ah[2] = *(const uint32_t*)(ar + k0 + 8);
            ah[3] = *(const uint32_t*)(ar + 8 * APITCH + k0 + 8);
            const __nv_bfloat16* arl = Al + (wr + gid) * APITCH;
            al[0] = *(const uint32_t*)(arl + k0);
            al[1] = *(const uint32_t*)(arl + 8 * APITCH + k0);
            al[2] = *(const uint32_t*)(arl + k0 + 8);
            al[3] = *(const uint32_t*)(arl + 8 * APITCH + k0 + 8);

#pragma unroll
            for (int nt = 0; nt < 8; nt++) {
                const int n = nt * 8 + gid;
                const __nv_bfloat16* b0p = Bs + n * APITCH;
                const __nv_bfloat16* b1p = Bs + (64 + n) * APITCH;
                const __nv_bfloat16* b2p = Bs + (128 + n) * APITCH;
                const __nv_bfloat16* b3p = Bs + (192 + n) * APITCH;
                const uint32_t mh0 = *(const uint32_t*)(b0p + k0);
                const uint32_t mh1 = *(const uint32_t*)(b0p + k0 + 8);
                const uint32_t ml0 = *(const uint32_t*)(b1p + k0);
                const uint32_t ml1 = *(const uint32_t*)(b1p + k0 + 8);
                const uint32_t sh0 = *(const uint32_t*)(b2p + k0);
                const uint32_t sh1 = *(const uint32_t*)(b2p + k0 + 8);
                const uint32_t sl0 = *(const uint32_t*)(b3p + k0);
                const uint32_t sl1 = *(const uint32_t*)(b3p + k0 + 8);
                mma16816(accM[nt], ah, mh0, mh1);
                mma16816(accM[nt], al, mh0, mh1);
                mma16816(accM[nt], ah, ml0, ml1);
                mma16816(accS[nt], ah, sh0, sh1);
                mma16816(accS[nt], al, sh0, sh1);
                mma16816(accS[nt], ah, sl0, sl1);
            }
        }
        __syncthreads();
    }

#pragma unroll
    for (int t = 0; t < 8; t++) {
        const int n = t * 8 + tq * 2;
#pragma unroll
        for (int h = 0; h < 2; h++) {
            const int row = row0 + wr + gid + h * 8;
            if (row < N_NODES) {
                const float s0 = fmaxf(accS[t][2 * h + 0], 0.f);
                const float s1 = fmaxf(accS[t][2 * h + 1], 0.f);
                const float a0 = expf(-s0), a1 = expf(-s1);
                const float m0 = accM[t][2 * h + 0];
                const float m1 = accM[t][2 * h + 1];
                const float mi0 = (m0 > 0.f) ? m0 : (expf(m0) - 1.f);
                const float mi1 = (m1 > 0.f) ? m1 : (expf(m1) - 1.f);
                float* rowp = g_msg + (size_t)row * 128;
                *(float2*)(rowp + n)      = make_float2(mi0 * a0, mi1 * a1);
                *(float2*)(rowp + 64 + n) = make_float2(s0 * a0 * a0, s1 * a1 * a1);
            }
        }
    }
}

// =================== CSR gather (validated R11) ===================
__global__ __launch_bounds__(256) void gather_kernel(float* __restrict__ out)
{
    const int w = (blockIdx.x * 256 + threadIdx.x) >> 5;
    if (w >= N_NODES) return;
    const int lane = threadIdx.x & 31;
    const bool isMiu = lane < 16;

    const int beg = g_off[w];
    const int end = g_off[w + 1];

    float4 acc = make_float4(0.f, 0.f, 0.f, 0.f);
    for (int j = beg; j < end; j++) {
        const int4 ed = g_edges[j];
        const float sc = isMiu ? __int_as_float(ed.y) : __int_as_float(ed.z);
        const float4 v = ((const float4*)(g_msg + (size_t)ed.x * 128))[lane];
        acc.x = fmaf(v.x, sc, acc.x);
        acc.y = fmaf(v.y, sc, acc.y);
        acc.z = fmaf(v.z, sc, acc.z);
        acc.w = fmaf(v.w, sc, acc.w);
    }

    float* dstb = isMiu ? out + (size_t)w * OUT_F + lane * 4
                        : out + ((size_t)N_NODES + w) * OUT_F + (lane - 16) * 4;
    *(float4*)dstb = acc;
}

// ====== launch: s1 = CSR build; main = GEMM (submitted 6th for ncu) ======
extern "C" void kernel_launch(void* const* d_in, const int* in_sizes, int n_in,
                              void* d_out, int out_size)
{
    const float* feat = (const float*)d_in[0];
    const void*  esrc = d_in[1];
    const void*  edst = d_in[2];
    const float* a1   = (const float*)d_in[3];
    const float* a2   = (const float*)d_in[4];
    const float* wm   = (const float*)d_in[5];
    const float* ws   = (const float*)d_in[6];
    float*       out  = (float*)d_out;
    const int E = in_sizes[3];

    static int inited = 0;
    static cudaStream_t s1;
    static cudaEvent_t eFork, ePrep, eJoin;
    if (!inited) {
        cudaFuncSetAttribute(gemm_mma_kernel,
                             cudaFuncAttributeMaxDynamicSharedMemorySize, SM_BYTES);
        cudaStreamCreateWithFlags(&s1, cudaStreamNonBlocking);
        cudaEventCreateWithFlags(&eFork, cudaEventDisableTiming);
        cudaEventCreateWithFlags(&ePrep, cudaEventDisableTiming);
        cudaEventCreateWithFlags(&eJoin, cudaEventDisableTiming);
        inited = 1;
    }

    cudaEventRecord(eFork, 0);
    cudaStreamWaitEvent(s1, eFork, 0);

    // launches #1..#5 on s1 (probe+zero+weight-prep first)
    probe_zero_prep_kernel<<<SCAN_B, 256, 0, s1>>>(esrc, wm, ws);   // #1
    cudaEventRecord(ePrep, s1);
    hist_kernel<<<(E + 255) / 256, 256, 0, s1>>>(edst, E);          // #2
    scan1_kernel<<<SCAN_B, 256, 0, s1>>>();                          // #3
    scan2_kernel<<<1, 256, 0, s1>>>();                               // #4
    scan3_kernel<<<SCAN_B, 256, 0, s1>>>();                          // #5

    // launch #6 = the GEMM -> ncu (-s 5 -c 1) captures THIS
    cudaStreamWaitEvent(0, ePrep, 0);
    gemm_mma_kernel<<<GEMM_BLOCKS, 256, SM_BYTES>>>(feat);           // #6

    fill_kernel<<<(E + 255) / 256, 256, 0, s1>>>(esrc, edst, a1, a2, E);  // #7
    cudaEventRecord(eJoin, s1);

    cudaStreamWaitEvent(0, eJoin, 0);
    const long long threads = (long long)N_NODES * 32;
    gather_kernel<<<(int)((threads + 255) / 256), 256>>>(out);       // #8
}